// round 16
// baseline (speedup 1.0000x reference)
#include <cuda_runtime.h>
#include <cstdint>
#include <cstddef>

#define B_ 8
#define N_ 16384
#define S_ 1024
#define K_ 32
#define NCC (B_*S_)                 // 8192 centers
#define NROWS (NCC*K_)              // 262144 grouped rows
#define R2_ 0.04f
#define CBLKS (NROWS/64)            // 4096 conv blocks (64 rows each)

// ---------------- device scratch (static; allocation APIs banned) ----------------
__device__ __align__(16) float g_centers[NCC*3];
__device__ int                 g_nbr[NROWS];
__device__ __align__(16) float g_h1[(size_t)NROWS*64];          // 64 MiB (reused sem/geo)
__device__ __align__(16) float g_sum[(size_t)128*CBLKS];        // channel-major partial sums
__device__ __align__(16) float g_ssq[(size_t)128*CBLKS];        // channel-major partial sumsq
__device__ __align__(16) float g_mx[(size_t)NCC*128];           // per-center raw-h2 max
__device__ __align__(16) float g_mn[(size_t)NCC*128];           // per-center raw-h2 min
__device__ __align__(16) float g_a[128];                        // BN scale
__device__ __align__(16) float g_c[128];                        // BN shift

// ---------------- helpers ----------------
__device__ __forceinline__ uint32_t s2u(const void* p) {
    return (uint32_t)__cvta_generic_to_shared(p);
}
__device__ __forceinline__ uint32_t mapa_u32(uint32_t a, int r) {
    uint32_t ret;
    asm("mapa.shared::cluster.u32 %0, %1, %2;" : "=r"(ret) : "r"(a), "r"(r));
    return ret;
}
__device__ __forceinline__ void st_rem64(uint32_t a, unsigned long long v) {
    asm volatile("st.shared::cluster.u64 [%0], %1;" :: "r"(a), "l"(v) : "memory");
}
__device__ __forceinline__ unsigned long long ld_vol64(const void* p) {
    unsigned long long v;
    asm volatile("ld.volatile.shared.u64 %0, [%1];" : "=l"(v) : "r"(s2u(p)));
    return v;
}
__device__ __forceinline__ void st_vol64(const void* p, unsigned long long v) {
    asm volatile("st.volatile.shared.u64 [%0], %1;" :: "r"(s2u(p)), "l"(v) : "memory");
}
// packed f32x2 (proven passing R12/R14)
__device__ __forceinline__ unsigned long long pack2(float x) {
    unsigned long long r;
    asm("mov.b64 %0, {%1, %1};" : "=l"(r) : "f"(x));
    return r;
}
__device__ __forceinline__ unsigned long long fma2(unsigned long long a,
                                                   unsigned long long b,
                                                   unsigned long long c) {
    unsigned long long d;
    asm("fma.rn.f32x2 %0, %1, %2, %3;" : "=l"(d) : "l"(a), "l"(b), "l"(c));
    return d;
}
__device__ __forceinline__ float2 unpack2(unsigned long long v) {
    float2 f;
    asm("mov.b64 {%0, %1}, %2;" : "=f"(f.x), "=f"(f.y) : "l"(v));
    return f;
}

// =====================================================================
// FPS: 8-CTA cluster per batch, tagged-word cross-CTA exchange (R10),
// HYBRID intra-CTA: warp records via tagged words (warp0-only spin,
// 16 lanes), center broadcast via plain SMEM + __syncthreads (the part
// R13 proved must NOT be a 512-thread spin).
// Selection order: max dist, then min index (bitwise == u64-key method).
// =====================================================================
#define FPS_C 8
#define FPS_T 512

__global__ __launch_bounds__(FPS_T, 1) __cluster_dims__(FPS_C, 1, 1)
void fps_kernel(const float* __restrict__ pos) {
    // per-warp winner: [0]=(dist<<32)|(seq<<16)|idx, [1..3]=(coord<<32)|seq
    __shared__ __align__(16) unsigned long long wrec[16][4];
    __shared__ __align__(16) unsigned long long rec[FPS_C][4];
    __shared__ float sbc[3];

    const int rank = blockIdx.x & (FPS_C - 1);
    const int b    = blockIdx.x >> 3;
    const int tid  = threadIdx.x;
    const int lane = tid & 31, wid = tid >> 5;
    const float* p = pos + (size_t)b * N_ * 3;

    if (tid < 64) ((unsigned long long*)wrec)[tid] = 0ull;
    if (tid >= 64 && tid < 64 + FPS_C * 4) ((unsigned long long*)rec)[tid - 64] = 0ull;
    __syncthreads();
    asm volatile("barrier.cluster.arrive.aligned;" ::: "memory");
    asm volatile("barrier.cluster.wait.aligned;"   ::: "memory");

    float qx[4], qy[4], qz[4], dist[4];
#pragma unroll
    for (int j = 0; j < 4; j++) {
        int g = rank * 2048 + j * FPS_T + tid;
        qx[j] = p[g*3]; qy[j] = p[g*3+1]; qz[j] = p[g*3+2];
        dist[j] = 1e10f;
    }
    float cx = p[0], cy = p[1], cz = p[2];

    for (int s = 0; s < S_; s++) {
        if (rank == 0 && tid == 0) {
            size_t cc = (size_t)b * S_ + s;
            g_centers[cc*3+0] = cx; g_centers[cc*3+1] = cy; g_centers[cc*3+2] = cz;
        }
        if (s == S_ - 1) break;

        // ---- update dists + per-thread argmax (strict > => smallest idx on tie) ----
        float best = -1.0f, bx = 0.f, by = 0.f, bz = 0.f;
        int bidx = 0;
#pragma unroll
        for (int j = 0; j < 4; j++) {
            float dx = qx[j] - cx, dy = qy[j] - cy, dz = qz[j] - cz;
            float d  = fmaf(dz, dz, fmaf(dy, dy, dx * dx));
            float nd = fminf(dist[j], d);
            dist[j]  = nd;
            if (nd > best) { best = nd; bx = qx[j]; by = qy[j]; bz = qz[j];
                             bidx = rank * 2048 + j * FPS_T + tid; }
        }

        const unsigned seq = (unsigned)s + 1u;   // 1..1023

        // ---- warp reduce: max dist bits, then min idx among holders ----
        unsigned db = __float_as_uint(best);
        unsigned wd = __reduce_max_sync(0xFFFFFFFFu, db);
        unsigned cand = (db == wd) ? (unsigned)bidx : 0xFFFFFFFFu;
        unsigned wi = __reduce_min_sync(0xFFFFFFFFu, cand);
        if (db == wd && (unsigned)bidx == wi) {   // unique owner lane
            st_vol64(&wrec[wid][0],
                     ((unsigned long long)wd << 32) | (seq << 16) | (wi & 0xFFFFu));
            st_vol64(&wrec[wid][1],
                     ((unsigned long long)__float_as_uint(bx) << 32) | seq);
            st_vol64(&wrec[wid][2],
                     ((unsigned long long)__float_as_uint(by) << 32) | seq);
            st_vol64(&wrec[wid][3],
                     ((unsigned long long)__float_as_uint(bz) << 32) | seq);
        }
        // NO barrier here: warp0 spins on the tagged warp records.

        if (wid == 0) {
            // ---- collect 16 warp records (lanes 0-15 spin) ----
            unsigned d2 = 0u, i2 = 0xFFFFFFFFu;
            float fx = 0.f, fy = 0.f, fz = 0.f;
            bool need = (lane < 16);
            for (;;) {
                if (need) {
                    unsigned long long v0 = ld_vol64(&wrec[lane][0]);
                    unsigned long long v1 = ld_vol64(&wrec[lane][1]);
                    unsigned long long v2 = ld_vol64(&wrec[lane][2]);
                    unsigned long long v3 = ld_vol64(&wrec[lane][3]);
                    if ((((unsigned)v0 >> 16) & 0xFFFFu) == seq &&
                        (unsigned)v1 == seq && (unsigned)v2 == seq &&
                        (unsigned)v3 == seq) {
                        d2 = (unsigned)(v0 >> 32);
                        i2 = (unsigned)v0 & 0xFFFFu;
                        fx = __uint_as_float((unsigned)(v1 >> 32));
                        fy = __uint_as_float((unsigned)(v2 >> 32));
                        fz = __uint_as_float((unsigned)(v3 >> 32));
                        need = false;
                    }
                }
                if (__all_sync(0xFFFFFFFFu, !need)) break;
            }

            // ---- CTA combine: max dist, min idx among holders ----
            unsigned wd2 = __reduce_max_sync(0xFFFFFFFFu, d2);
            unsigned c2  = (d2 == wd2) ? i2 : 0xFFFFFFFFu;
            unsigned wi2 = __reduce_min_sync(0xFFFFFFFFu, c2);
            unsigned omask = __ballot_sync(0xFFFFFFFFu,
                                           (lane < 16) && d2 == wd2 && i2 == wi2);
            int owner = __ffs(omask) - 1;
            float ox = __shfl_sync(0xFFFFFFFFu, fx, owner);
            float oy = __shfl_sync(0xFFFFFFFFu, fy, owner);
            float oz = __shfl_sync(0xFFFFFFFFu, fz, owner);

            // ---- publish to 8 peer CTAs (tagged; lane r -> peer r) ----
            if (lane < FPS_C) {
                unsigned nlo = (unsigned)(N_ - (int)wi2);
                unsigned long long w0 =
                    ((unsigned long long)wd2 << 32) | (seq << 16) | nlo;
                unsigned long long w1 =
                    ((unsigned long long)__float_as_uint(ox) << 32) | seq;
                unsigned long long w2 =
                    ((unsigned long long)__float_as_uint(oy) << 32) | seq;
                unsigned long long w3 =
                    ((unsigned long long)__float_as_uint(oz) << 32) | seq;
                uint32_t ra = mapa_u32(s2u(&rec[rank][0]), lane);
                st_rem64(ra,      w0);
                st_rem64(ra + 8,  w1);
                st_rem64(ra + 16, w2);
                st_rem64(ra + 24, w3);
            }

            // ---- spin: lane r waits for peer slot r ----
            unsigned kd = 0, knlo = 0;
            float gx = 0.f, gy = 0.f, gz = 0.f;
            bool need2 = (lane < FPS_C);
            for (;;) {
                if (need2) {
                    unsigned long long v0 = ld_vol64(&rec[lane][0]);
                    unsigned long long v1 = ld_vol64(&rec[lane][1]);
                    unsigned long long v2 = ld_vol64(&rec[lane][2]);
                    unsigned long long v3 = ld_vol64(&rec[lane][3]);
                    if ((((unsigned)v0 >> 16) & 0xFFFFu) == seq &&
                        (unsigned)v1 == seq && (unsigned)v2 == seq &&
                        (unsigned)v3 == seq) {
                        kd   = (unsigned)(v0 >> 32);
                        knlo = (unsigned)v0 & 0xFFFFu;
                        gx = __uint_as_float((unsigned)(v1 >> 32));
                        gy = __uint_as_float((unsigned)(v2 >> 32));
                        gz = __uint_as_float((unsigned)(v3 >> 32));
                        need2 = false;
                    }
                }
                if (__all_sync(0xFFFFFFFFu, !need2)) break;
            }

            // ---- combine 8 records: max dist, then max (N-idx) = min idx ----
            unsigned hi  = (lane < FPS_C) ? kd : 0u;
            unsigned wdh = __reduce_max_sync(0xFFFFFFFFu, hi);
            unsigned lo2 = (lane < FPS_C && kd == wdh) ? knlo : 0u;
            unsigned wlo = __reduce_max_sync(0xFFFFFFFFu, lo2);
            if (lane < FPS_C && kd == wdh && knlo == wlo) {
                sbc[0] = gx; sbc[1] = gy; sbc[2] = gz;
            }
        }
        __syncthreads();                  // orders sbc write -> all reads
        cx = sbc[0]; cy = sbc[1]; cz = sbc[2];
    }

    asm volatile("barrier.cluster.arrive.aligned;" ::: "memory");
    asm volatile("barrier.cluster.wait.aligned;"   ::: "memory");
}

// =====================================================================
// Ball query: unchanged.
// =====================================================================
__global__ __launch_bounds__(256)
void ballquery_kernel(const float* __restrict__ pos) {
    __shared__ int buf[8][32];
    const int wloc = threadIdx.x >> 5;
    const int lane = threadIdx.x & 31;
    const int cc = blockIdx.x * 8 + wloc;
    const int b = cc >> 10;
    const float* p = pos + (size_t)b * N_ * 3;
    const float cx = g_centers[cc*3], cy = g_centers[cc*3+1], cz = g_centers[cc*3+2];

    int count = 0, first = 0;
    bool haveFirst = false;
    for (int base = 0; base < N_; base += 32) {
        int j = base + lane;
        float x = p[j*3], y = p[j*3+1], z = p[j*3+2];
        float dx = cx - x, dy = cy - y, dz = cz - z;
        float d = fmaf(dz, dz, fmaf(dy, dy, dx * dx));
        bool in = (d <= R2_);
        unsigned m = __ballot_sync(0xFFFFFFFFu, in);
        if (m) {
            if (!haveFirst) { first = base + __ffs(m) - 1; haveFirst = true; }
            int slot = count + __popc(m & ((1u << lane) - 1u));
            if (in && slot < 32) buf[wloc][slot] = j;
            count += __popc(m);
            if (count >= 32) break;
        }
    }
    __syncwarp();
    int v = (lane < count) ? buf[wloc][lane] : first;
    g_nbr[(size_t)cc * 32 + lane] = v;
}

// =====================================================================
// conv1: R15 warp-tile version (passing).
// =====================================================================
template<int CIN, bool GEO>
__global__ __launch_bounds__(256)
void conv1_kernel(const float* __restrict__ feat, const float* __restrict__ pos,
                  const float* __restrict__ W, const float* __restrict__ bias) {
    constexpr int PAD = CIN + 1;
    __shared__ float Xs[64 * PAD];
    __shared__ float Ws[CIN * 64];
    __shared__ float st[256];
    const int row0 = blockIdx.x * 64;
    const int tid = threadIdx.x;

    for (int i = tid; i < CIN * 64 / 4; i += 256)
        ((float4*)Ws)[i] = ((const float4*)W)[i];

    if (!GEO) {
        for (int i = tid; i < 64 * 16; i += 256) {
            int r = i >> 4, c4 = (i & 15) * 4;
            int row = row0 + r;
            int j = g_nbr[row];
            int b = row >> 15;
            float4 v = *(const float4*)&feat[((size_t)b * N_ + j) * 64 + c4];
            float* xr = &Xs[r * PAD + c4];
            xr[0] = v.x; xr[1] = v.y; xr[2] = v.z; xr[3] = v.w;
        }
    } else {
        for (int i = tid; i < 64 * CIN; i += 256) {
            int r = i / CIN, c = i - r * CIN;
            int row = row0 + r;
            int cc = row >> 5;
            float v;
            if (c < 3) {
                v = g_centers[cc * 3 + c];
            } else {
                int j = g_nbr[row];
                int b = row >> 15;
                v = pos[((size_t)b * N_ + j) * 3 + (c - 3)];
            }
            Xs[r * PAD + c] = v;
        }
    }
    __syncthreads();

    const int warp = tid >> 5, lane = tid & 31;
    const int wr = warp & 1;
    const int wc = warp >> 1;
    const int lr = lane >> 2;
    const int lc = lane & 3;
    const int rb = wr * 32 + lr * 4;
    const int cb = wc * 16 + lc * 4;

    unsigned long long acc2[4][2];
#pragma unroll
    for (int i = 0; i < 4; i++) { acc2[i][0] = 0ull; acc2[i][1] = 0ull; }

#pragma unroll
    for (int k = 0; k < CIN; k++) {
        unsigned long long xx[4];
#pragma unroll
        for (int i = 0; i < 4; i++) xx[i] = pack2(Xs[(rb + i) * PAD + k]);
        ulonglong2 wv = *(const ulonglong2*)&Ws[k * 64 + cb];
#pragma unroll
        for (int i = 0; i < 4; i++) {
            acc2[i][0] = fma2(xx[i], wv.x, acc2[i][0]);
            acc2[i][1] = fma2(xx[i], wv.y, acc2[i][1]);
        }
    }

    float bb[4];
#pragma unroll
    for (int j = 0; j < 4; j++) bb[j] = bias[cb + j];
    float sl[4] = {0, 0, 0, 0}, ssl[4] = {0, 0, 0, 0};
#pragma unroll
    for (int i = 0; i < 4; i++) {
        float2 a0 = unpack2(acc2[i][0]);
        float2 a1 = unpack2(acc2[i][1]);
        float4 hv;
        hv.x = a0.x + bb[0]; hv.y = a0.y + bb[1];
        hv.z = a1.x + bb[2]; hv.w = a1.y + bb[3];
        *(float4*)&g_h1[(size_t)(row0 + rb + i) * 64 + cb] = hv;
        sl[0] += hv.x; ssl[0] += hv.x * hv.x;
        sl[1] += hv.y; ssl[1] += hv.y * hv.y;
        sl[2] += hv.z; ssl[2] += hv.z * hv.z;
        sl[3] += hv.w; ssl[3] += hv.w * hv.w;
    }
#pragma unroll
    for (int off = 16; off >= 4; off >>= 1) {
#pragma unroll
        for (int j = 0; j < 4; j++) {
            sl[j]  += __shfl_down_sync(0xFFFFFFFFu, sl[j],  off);
            ssl[j] += __shfl_down_sync(0xFFFFFFFFu, ssl[j], off);
        }
    }
    if (lr == 0) {
#pragma unroll
        for (int j = 0; j < 4; j++) {
            st[wr * 64 + cb + j]       = sl[j];
            st[128 + wr * 64 + cb + j] = ssl[j];
        }
    }
    __syncthreads();
    if (tid < 64) {
        float S  = st[tid] + st[64 + tid];
        float SS = st[128 + tid] + st[192 + tid];
        g_sum[(size_t)tid * CBLKS + blockIdx.x] = S;
        g_ssq[(size_t)tid * CBLKS + blockIdx.x] = SS;
    }
}

// =====================================================================
// conv2: R14 version (passing) — 32x32 warp tiles, shfl-tree epilogue.
// =====================================================================
#define C2_XS (64 * 65)
#define C2_SMEM ((C2_XS + 64 * 128) * (int)sizeof(float))

__global__ __launch_bounds__(256)
void conv2_kernel(const float* __restrict__ W, const float* __restrict__ bias) {
    extern __shared__ float dsm[];
    float* Xs = dsm;
    float* Ws = dsm + C2_XS;
    const int row0 = blockIdx.x * 64;
    const int tid = threadIdx.x;

    for (int i = tid; i < 64 * 128 / 4; i += 256)
        ((float4*)Ws)[i] = ((const float4*)W)[i];
    for (int i = tid; i < 64 * 16; i += 256) {
        int r = i >> 4, c4 = (i & 15) * 4;
        float4 h = *(const float4*)&g_h1[(size_t)(row0 + r) * 64 + c4];
        float4 A = *(const float4*)&g_a[c4];
        float4 C = *(const float4*)&g_c[c4];
        float* xr = &Xs[r * 65 + c4];
        xr[0] = fmaxf(0.0f, fmaf(A.x, h.x, C.x));
        xr[1] = fmaxf(0.0f, fmaf(A.y, h.y, C.y));
        xr[2] = fmaxf(0.0f, fmaf(A.z, h.z, C.z));
        xr[3] = fmaxf(0.0f, fmaf(A.w, h.w, C.w));
    }
    __syncthreads();

    const int warp = tid >> 5, lane = tid & 31;
    const int wr = warp & 1;
    const int wc = warp >> 1;
    const int lr = lane >> 2;
    const int lc = lane & 3;
    const int rb = wr * 32 + lr * 4;
    const int cb = wc * 32 + lc * 8;

    unsigned long long acc2[4][4];
#pragma unroll
    for (int i = 0; i < 4; i++)
#pragma unroll
        for (int j = 0; j < 4; j++) acc2[i][j] = 0ull;

#pragma unroll 8
    for (int k = 0; k < 64; k++) {
        unsigned long long xx[4];
#pragma unroll
        for (int i = 0; i < 4; i++) xx[i] = pack2(Xs[(rb + i) * 65 + k]);
        ulonglong2 wa = *(const ulonglong2*)&Ws[k * 128 + cb];
        ulonglong2 wb = *(const ulonglong2*)&Ws[k * 128 + cb + 4];
#pragma unroll
        for (int i = 0; i < 4; i++) {
            acc2[i][0] = fma2(xx[i], wa.x, acc2[i][0]);
            acc2[i][1] = fma2(xx[i], wa.y, acc2[i][1]);
            acc2[i][2] = fma2(xx[i], wb.x, acc2[i][2]);
            acc2[i][3] = fma2(xx[i], wb.y, acc2[i][3]);
        }
    }

    float acc[4][8];
#pragma unroll
    for (int i = 0; i < 4; i++)
#pragma unroll
        for (int j = 0; j < 4; j++) {
            float2 v = unpack2(acc2[i][j]);
            acc[i][j * 2]     = v.x;
            acc[i][j * 2 + 1] = v.y;
        }

    float bb[8];
#pragma unroll
    for (int j = 0; j < 8; j++) bb[j] = bias[cb + j];
    float sl[8], ssl[8], mxl[8], mnl[8];
#pragma unroll
    for (int j = 0; j < 8; j++) {
        sl[j] = 0.0f; ssl[j] = 0.0f;
        mxl[j] = -3.402823466e38f; mnl[j] = 3.402823466e38f;
    }
#pragma unroll
    for (int i = 0; i < 4; i++)
#pragma unroll
        for (int j = 0; j < 8; j++) {
            float h = acc[i][j] + bb[j];
            sl[j] += h; ssl[j] += h * h;
            mxl[j] = fmaxf(mxl[j], h); mnl[j] = fminf(mnl[j], h);
        }

#pragma unroll
    for (int off = 16; off >= 4; off >>= 1) {
#pragma unroll
        for (int j = 0; j < 8; j++) {
            sl[j]  += __shfl_down_sync(0xFFFFFFFFu, sl[j],  off);
            ssl[j] += __shfl_down_sync(0xFFFFFFFFu, ssl[j], off);
            mxl[j] = fmaxf(mxl[j], __shfl_down_sync(0xFFFFFFFFu, mxl[j], off));
            mnl[j] = fminf(mnl[j], __shfl_down_sync(0xFFFFFFFFu, mnl[j], off));
        }
    }

    float* st = Xs;
    __syncthreads();
    if (lr == 0) {
        int blk = blockIdx.x;
#pragma unroll
        for (int j = 0; j < 8; j++) {
            int c = cb + j;
            g_mx[(size_t)(blk * 2 + wr) * 128 + c] = mxl[j];
            g_mn[(size_t)(blk * 2 + wr) * 128 + c] = mnl[j];
            st[wr * 128 + c]       = sl[j];
            st[256 + wr * 128 + c] = ssl[j];
        }
    }
    __syncthreads();
    if (tid < 128) {
        float S  = st[tid] + st[128 + tid];
        float SS = st[256 + tid] + st[384 + tid];
        g_sum[(size_t)tid * CBLKS + blockIdx.x] = S;
        g_ssq[(size_t)tid * CBLKS + blockIdx.x] = SS;
    }
}

// =====================================================================
// BN finalize: float4 partial reads, fp64 tree (R13 version, passing).
// =====================================================================
__global__ __launch_bounds__(256)
void finalize_stats(const float* __restrict__ gamma,
                    const float* __restrict__ beta, int C) {
    const int ch = blockIdx.x;
    const int t = threadIdx.x;     // 256
    __shared__ double rs[256], rss[256];
    double S = 0.0, SS = 0.0;
#pragma unroll
    for (int i = 0; i < 4; i++) {
        float4 a = *(const float4*)&g_sum[(size_t)ch * CBLKS + i * 1024 + t * 4];
        float4 b = *(const float4*)&g_ssq[(size_t)ch * CBLKS + i * 1024 + t * 4];
        S  += (double)a.x + (double)a.y + (double)a.z + (double)a.w;
        SS += (double)b.x + (double)b.y + (double)b.z + (double)b.w;
    }
    rs[t] = S; rss[t] = SS;
    __syncthreads();
    for (int off = 128; off; off >>= 1) {
        if (t < off) { rs[t] += rs[t + off]; rss[t] += rss[t + off]; }
        __syncthreads();
    }
    if (t == 0) {
        double inv_n = 1.0 / (double)NROWS;
        double mu  = rs[0] * inv_n;
        double var = rss[0] * inv_n - mu * mu;
        double a = (double)gamma[ch] / sqrt(var + 1e-5);
        g_a[ch] = (float)a;
        g_c[ch] = (float)((double)beta[ch] - mu * a);
    }
}

// =====================================================================
// Output: relu(a * extreme(h2) + c).
// =====================================================================
__global__ void final_out(float* __restrict__ out) {
    const int cc = blockIdx.x;
    const int ch = threadIdx.x;    // 128
    float a = g_a[ch];
    float ext = (a >= 0.0f) ? g_mx[(size_t)cc * 128 + ch] : g_mn[(size_t)cc * 128 + ch];
    out[(size_t)cc * 128 + ch] = fmaxf(0.0f, fmaf(a, ext, g_c[ch]));
}

// =====================================================================
extern "C" void kernel_launch(void* const* d_in, const int* in_sizes, int n_in,
                              void* d_out, int out_size) {
    const float* pos     = (const float*)d_in[0];
    const float* feat    = (const float*)d_in[1];
    const float* w_sem1  = (const float*)d_in[2];
    const float* b_sem1  = (const float*)d_in[3];
    const float* g_sem1  = (const float*)d_in[4];
    const float* be_sem1 = (const float*)d_in[5];
    const float* w_sem2  = (const float*)d_in[6];
    const float* b_sem2  = (const float*)d_in[7];
    const float* g_sem2  = (const float*)d_in[8];
    const float* be_sem2 = (const float*)d_in[9];
    const float* w_geo1  = (const float*)d_in[10];
    const float* b_geo1  = (const float*)d_in[11];
    const float* g_geo1  = (const float*)d_in[12];
    const float* be_geo1 = (const float*)d_in[13];
    const float* w_geo2  = (const float*)d_in[14];
    const float* b_geo2  = (const float*)d_in[15];
    const float* g_geo2  = (const float*)d_in[16];
    const float* be_geo2 = (const float*)d_in[17];
    float* out = (float*)d_out;

    cudaFuncSetAttribute(conv2_kernel, cudaFuncAttributeMaxDynamicSharedMemorySize,
                         C2_SMEM);

    fps_kernel<<<B_ * FPS_C, FPS_T>>>(pos);
    ballquery_kernel<<<NCC / 8, 256>>>(pos);

    // ---- SEM branch ----
    conv1_kernel<64, false><<<CBLKS, 256>>>(feat, nullptr, w_sem1, b_sem1);
    finalize_stats<<<64, 256>>>(g_sem1, be_sem1, 64);
    conv2_kernel<<<CBLKS, 256, C2_SMEM>>>(w_sem2, b_sem2);
    finalize_stats<<<128, 256>>>(g_sem2, be_sem2, 128);
    final_out<<<NCC, 128>>>(out);

    // ---- GEO branch (reuses scratch sequentially; stream-ordered) ----
    conv1_kernel<6, true><<<CBLKS, 256>>>(nullptr, pos, w_geo1, b_geo1);
    finalize_stats<<<64, 256>>>(g_geo1, be_geo1, 64);
    conv2_kernel<<<CBLKS, 256, C2_SMEM>>>(w_geo2, b_geo2);
    finalize_stats<<<128, 256>>>(g_geo2, be_geo2, 128);
    final_out<<<NCC, 128>>>(out + (size_t)NCC * 128);
}

// round 17
// speedup vs baseline: 1.2086x; 1.2086x over previous
#include <cuda_runtime.h>
#include <cstdint>
#include <cstddef>

#define B_ 8
#define N_ 16384
#define S_ 1024
#define K_ 32
#define NCC (B_*S_)                 // 8192 centers
#define NROWS (NCC*K_)              // 262144 grouped rows
#define R2_ 0.04f
#define CBLKS (NROWS/64)            // 4096 64-row blocks
#define WBLK (NROWS/128)            // 2048 worker CTAs (128 rows each)

// ---------------- device scratch (static; allocation APIs banned) ----------------
__device__ unsigned long long  g_ctag[NCC*3];                   // tagged centers
__device__ __align__(16) float g_h1 [(size_t)NROWS*64];         // sem h1
__device__ __align__(16) float g_h1b[(size_t)NROWS*64];         // geo h1
__device__ __align__(16) float g_sumA[(size_t)64*CBLKS],  g_ssqA[(size_t)64*CBLKS];
__device__ __align__(16) float g_sumB[(size_t)64*CBLKS],  g_ssqB[(size_t)64*CBLKS];
__device__ __align__(16) float g_sumC[(size_t)128*CBLKS], g_ssqC[(size_t)128*CBLKS];
__device__ __align__(16) float g_mx[(size_t)NCC*128];
__device__ __align__(16) float g_mn[(size_t)NCC*128];
__device__ __align__(16) float g_a[128];
__device__ __align__(16) float g_c[128];

// ---------------- helpers ----------------
__device__ __forceinline__ uint32_t s2u(const void* p) {
    return (uint32_t)__cvta_generic_to_shared(p);
}
__device__ __forceinline__ uint32_t mapa_u32(uint32_t a, int r) {
    uint32_t ret;
    asm("mapa.shared::cluster.u32 %0, %1, %2;" : "=r"(ret) : "r"(a), "r"(r));
    return ret;
}
__device__ __forceinline__ void st_rem64(uint32_t a, unsigned long long v) {
    asm volatile("st.shared::cluster.u64 [%0], %1;" :: "r"(a), "l"(v) : "memory");
}
__device__ __forceinline__ unsigned long long ld_vol64(const void* p) {
    unsigned long long v;
    asm volatile("ld.volatile.shared.u64 %0, [%1];" : "=l"(v) : "r"(s2u(p)));
    return v;
}
__device__ __forceinline__ void stg_vol64(unsigned long long* p, unsigned long long v) {
    asm volatile("st.volatile.global.u64 [%0], %1;" :: "l"(p), "l"(v) : "memory");
}
__device__ __forceinline__ unsigned long long ldg_vol64(const unsigned long long* p) {
    unsigned long long v;
    asm volatile("ld.volatile.global.u64 %0, [%1];" : "=l"(v) : "l"(p));
    return v;
}
__device__ __forceinline__ unsigned long long pack2(float x) {
    unsigned long long r;
    asm("mov.b64 %0, {%1, %1};" : "=l"(r) : "f"(x));
    return r;
}
__device__ __forceinline__ unsigned long long fma2(unsigned long long a,
                                                   unsigned long long b,
                                                   unsigned long long c) {
    unsigned long long d;
    asm("fma.rn.f32x2 %0, %1, %2, %3;" : "=l"(d) : "l"(a), "l"(b), "l"(c));
    return d;
}
__device__ __forceinline__ float2 unpack2(unsigned long long v) {
    float2 f;
    asm("mov.b64 {%0, %1}, %2;" : "=f"(f.x), "=f"(f.y) : "l"(v));
    return f;
}

// =====================================================================
// Fused FPS + (ballquery + conv1 sem/geo) workers.
// Bids 0..63: exact R14 FPS (8-CTA clusters per batch), centers
// published as tagged 8B global words. Bids >= 64: worker p = bid-64
// handles centers 4p..4p+3 (128 rows): poll centers, ballquery, gather,
// conv1 both branches (R15 math, bitwise identical), stats partials.
// =====================================================================
#define FPS_C 8
#define FPS_T 512
#define GRID_ (64 + WBLK)

// worker smem layout (floats)
#define WS_XSS 0                    // 128*65
#define WS_WSS (128*65)             // 64*64
#define WS_XSG (WS_WSS + 64*64)     // 128*7
#define WS_WSG (WS_XSG + 128*7)     // 6*64
#define WS_ST  (WS_WSG + 6*64)      // 2*256
#define WS_NBR (WS_ST + 512)        // 128 ints
#define WS_CX  (WS_NBR + 128)       // 12 floats
#define WS_FLOATS (WS_CX + 16)
#define FUSED_SMEM (WS_FLOATS * (int)sizeof(float))

__global__ __launch_bounds__(FPS_T, 1) __cluster_dims__(FPS_C, 1, 1)
void fused_kernel(const float* __restrict__ pos, const float* __restrict__ feat,
                  const float* __restrict__ w1, const float* __restrict__ b1,
                  const float* __restrict__ wg, const float* __restrict__ bg) {
    extern __shared__ float ws[];
    const int bid = blockIdx.x;
    const int tid = threadIdx.x;
    const int lane = tid & 31, wid = tid >> 5;

    if (bid < 64) {
        // ================= FPS (R14 exact, tagged center output) =================
        __shared__ unsigned wdist[16];
        __shared__ unsigned widx[16];
        __shared__ float wxs[16], wys[16], wzs[16];
        __shared__ __align__(16) unsigned long long rec[FPS_C][4];
        __shared__ float sbc[3];

        const int rank = bid & (FPS_C - 1);
        const int b    = bid >> 3;
        const float* p = pos + (size_t)b * N_ * 3;

        if (tid < FPS_C * 4) ((unsigned long long*)rec)[tid] = 0ull;
        __syncthreads();
        asm volatile("barrier.cluster.arrive.aligned;" ::: "memory");
        asm volatile("barrier.cluster.wait.aligned;"   ::: "memory");

        float qx[4], qy[4], qz[4], dist[4];
#pragma unroll
        for (int j = 0; j < 4; j++) {
            int g = rank * 2048 + j * FPS_T + tid;
            qx[j] = p[g*3]; qy[j] = p[g*3+1]; qz[j] = p[g*3+2];
            dist[j] = 1e10f;
        }
        float cx = p[0], cy = p[1], cz = p[2];

        for (int s = 0; s < S_; s++) {
            if (rank == 0 && tid == 0) {
                size_t cc = (size_t)b * S_ + s;
                unsigned long long tg = (unsigned long long)(s + 1);
                stg_vol64(&g_ctag[cc*3+0], ((unsigned long long)__float_as_uint(cx) << 32) | tg);
                stg_vol64(&g_ctag[cc*3+1], ((unsigned long long)__float_as_uint(cy) << 32) | tg);
                stg_vol64(&g_ctag[cc*3+2], ((unsigned long long)__float_as_uint(cz) << 32) | tg);
            }
            if (s == S_ - 1) break;

            float best = -1.0f, bx = 0.f, by = 0.f, bz = 0.f;
            int bidx = 0;
#pragma unroll
            for (int j = 0; j < 4; j++) {
                float dx = qx[j] - cx, dy = qy[j] - cy, dz = qz[j] - cz;
                float d  = fmaf(dz, dz, fmaf(dy, dy, dx * dx));
                float nd = fminf(dist[j], d);
                dist[j]  = nd;
                if (nd > best) { best = nd; bx = qx[j]; by = qy[j]; bz = qz[j];
                                 bidx = rank * 2048 + j * FPS_T + tid; }
            }

            unsigned db = __float_as_uint(best);
            unsigned wd = __reduce_max_sync(0xFFFFFFFFu, db);
            unsigned cand = (db == wd) ? (unsigned)bidx : 0xFFFFFFFFu;
            unsigned wi = __reduce_min_sync(0xFFFFFFFFu, cand);
            if (db == wd && (unsigned)bidx == wi) {
                wdist[wid] = wd; widx[wid] = wi;
                wxs[wid] = bx; wys[wid] = by; wzs[wid] = bz;
            }
            __syncthreads();

            const unsigned seq = (unsigned)s + 1u;

            if (wid == 0) {
                unsigned d2 = (lane < 16) ? wdist[lane] : 0u;
                unsigned i2 = (lane < 16) ? widx[lane]  : 0xFFFFFFFFu;
                unsigned wd2 = __reduce_max_sync(0xFFFFFFFFu, d2);
                unsigned c2  = (d2 == wd2) ? i2 : 0xFFFFFFFFu;
                unsigned wi2 = __reduce_min_sync(0xFFFFFFFFu, c2);
                unsigned omask = __ballot_sync(0xFFFFFFFFu,
                                               (lane < 16) && d2 == wd2 && i2 == wi2);
                int owner = __ffs(omask) - 1;

                if (lane < FPS_C) {
                    float ox = wxs[owner], oy = wys[owner], oz = wzs[owner];
                    unsigned nlo = (unsigned)(N_ - (int)wi2);
                    unsigned long long w0 =
                        ((unsigned long long)wd2 << 32) | (seq << 16) | nlo;
                    unsigned long long w1v =
                        ((unsigned long long)__float_as_uint(ox) << 32) | seq;
                    unsigned long long w2v =
                        ((unsigned long long)__float_as_uint(oy) << 32) | seq;
                    unsigned long long w3v =
                        ((unsigned long long)__float_as_uint(oz) << 32) | seq;
                    uint32_t ra = mapa_u32(s2u(&rec[rank][0]), lane);
                    st_rem64(ra,      w0);
                    st_rem64(ra + 8,  w1v);
                    st_rem64(ra + 16, w2v);
                    st_rem64(ra + 24, w3v);
                }

                unsigned kd = 0, knlo = 0;
                float fx = 0.f, fy = 0.f, fz = 0.f;
                bool need = (lane < FPS_C);
                for (;;) {
                    if (need) {
                        unsigned long long v0 = ld_vol64(&rec[lane][0]);
                        unsigned long long v1 = ld_vol64(&rec[lane][1]);
                        unsigned long long v2 = ld_vol64(&rec[lane][2]);
                        unsigned long long v3 = ld_vol64(&rec[lane][3]);
                        unsigned t0 = ((unsigned)v0 >> 16) & 0xFFFFu;
                        if (t0 == seq && (unsigned)v1 == seq &&
                            (unsigned)v2 == seq && (unsigned)v3 == seq) {
                            kd   = (unsigned)(v0 >> 32);
                            knlo = (unsigned)v0 & 0xFFFFu;
                            fx = __uint_as_float((unsigned)(v1 >> 32));
                            fy = __uint_as_float((unsigned)(v2 >> 32));
                            fz = __uint_as_float((unsigned)(v3 >> 32));
                            need = false;
                        }
                    }
                    if (__all_sync(0xFFFFFFFFu, !need)) break;
                }

                unsigned hi  = (lane < FPS_C) ? kd : 0u;
                unsigned wdh = __reduce_max_sync(0xFFFFFFFFu, hi);
                unsigned lo2 = (lane < FPS_C && kd == wdh) ? knlo : 0u;
                unsigned wlo = __reduce_max_sync(0xFFFFFFFFu, lo2);
                if (lane < FPS_C && kd == wdh && knlo == wlo) {
                    sbc[0] = fx; sbc[1] = fy; sbc[2] = fz;
                }
            }
            __syncthreads();
            cx = sbc[0]; cy = sbc[1]; cz = sbc[2];
        }

        asm volatile("barrier.cluster.arrive.aligned;" ::: "memory");
        asm volatile("barrier.cluster.wait.aligned;"   ::: "memory");
        return;
    }

    // ================= worker =================
    const int wp = bid - 64;            // 0..WBLK-1
    float* XsS = ws + WS_XSS;
    float* WsS = ws + WS_WSS;
    float* XsG = ws + WS_XSG;
    float* WsG = ws + WS_WSG;
    float* st  = ws + WS_ST;
    int*   nbr = (int*)(ws + WS_NBR);
    float* cxy = ws + WS_CX;

    // warps 0-3: poll center + ballquery; threads 128..511: load weights
    if (wid < 4) {
        const int cc = 4 * wp + wid;
        const int b = cc >> 10;
        const unsigned tag = (unsigned)((cc & 1023) + 1);
        float cx, cy, cz;
        if (lane == 0) {
            const unsigned long long* tp = &g_ctag[(size_t)cc * 3];
            unsigned long long u0, u1, u2;
            for (;;) {
                u0 = ldg_vol64(tp);
                if ((unsigned)u0 == tag) {
                    u1 = ldg_vol64(tp + 1);
                    u2 = ldg_vol64(tp + 2);
                    if ((unsigned)u1 == tag && (unsigned)u2 == tag) break;
                }
                __nanosleep(200);
            }
            cx = __uint_as_float((unsigned)(u0 >> 32));
            cy = __uint_as_float((unsigned)(u1 >> 32));
            cz = __uint_as_float((unsigned)(u2 >> 32));
        }
        __syncwarp();
        cx = __shfl_sync(0xFFFFFFFFu, cx, 0);
        cy = __shfl_sync(0xFFFFFFFFu, cy, 0);
        cz = __shfl_sync(0xFFFFFFFFu, cz, 0);
        if (lane == 0) { cxy[wid*3] = cx; cxy[wid*3+1] = cy; cxy[wid*3+2] = cz; }

        // ballquery (exact semantics of the passing kernel)
        const float* p = pos + (size_t)b * N_ * 3;
        int count = 0, first = 0;
        bool haveFirst = false;
        for (int base = 0; base < N_; base += 32) {
            int j = base + lane;
            float x = p[j*3], y = p[j*3+1], z = p[j*3+2];
            float dx = cx - x, dy = cy - y, dz = cz - z;
            float d = fmaf(dz, dz, fmaf(dy, dy, dx * dx));
            bool in = (d <= R2_);
            unsigned m = __ballot_sync(0xFFFFFFFFu, in);
            if (m) {
                if (!haveFirst) { first = base + __ffs(m) - 1; haveFirst = true; }
                int slot = count + __popc(m & ((1u << lane) - 1u));
                if (in && slot < 32) nbr[wid * 32 + slot] = j;
                count += __popc(m);
                if (count >= 32) break;
            }
        }
        __syncwarp();
        if (lane >= count) nbr[wid * 32 + lane] = first;
    } else if (tid >= 128) {
        for (int i = tid - 128; i < 1024 + 96; i += 384) {
            if (i < 1024) ((float4*)WsS)[i] = ((const float4*)w1)[i];
            else         ((float4*)WsG)[i - 1024] = ((const float4*)wg)[i - 1024];
        }
    }
    __syncthreads();

    // gather fills (rows 0..127 local; global row = wp*128 + r)
    for (int i = tid; i < 128 * 16; i += FPS_T) {
        int r = i >> 4, c4 = (i & 15) * 4;
        int j = nbr[(r >> 5) * 32 + (r & 31)];
        int b = (wp * 128 + r) >> 15;
        float4 v = *(const float4*)&feat[((size_t)b * N_ + j) * 64 + c4];
        float* xr = &XsS[r * 65 + c4];
        xr[0] = v.x; xr[1] = v.y; xr[2] = v.z; xr[3] = v.w;
    }
    for (int i = tid; i < 128 * 6; i += FPS_T) {
        int r = i / 6, c = i - r * 6;
        int lc4 = r >> 5;                 // local center 0..3
        float v;
        if (c < 3) v = cxy[lc4 * 3 + c];
        else {
            int j = nbr[lc4 * 32 + (r & 31)];
            int b = (wp * 128 + r) >> 15;
            v = pos[((size_t)b * N_ + j) * 3 + (c - 3)];
        }
        XsG[r * 7 + c] = v;
    }
    __syncthreads();

    // conv1 units: u = wid>>3 (rows u*64..+63), 8 warps each — R15 math.
    const int u  = wid >> 3;
    const int w8 = wid & 7;
    const int wr = w8 & 1;
    const int wc = w8 >> 1;
    const int lr = lane >> 2;
    const int lc = lane & 3;
    const int rb = wr * 32 + lr * 4;
    const int cb = wc * 16 + lc * 4;
    const size_t rowg = (size_t)wp * 128 + u * 64;
    const int blkcol = wp * 2 + u;
    float* Xu = XsS + u * 64 * 65;
    float* stu = st + u * 256;

    {   // ---- sem (CIN=64) ----
        unsigned long long acc2[4][2];
#pragma unroll
        for (int i = 0; i < 4; i++) { acc2[i][0] = 0ull; acc2[i][1] = 0ull; }
#pragma unroll 8
        for (int k = 0; k < 64; k++) {
            unsigned long long xx[4];
#pragma unroll
            for (int i = 0; i < 4; i++) xx[i] = pack2(Xu[(rb + i) * 65 + k]);
            ulonglong2 wv = *(const ulonglong2*)&WsS[k * 64 + cb];
#pragma unroll
            for (int i = 0; i < 4; i++) {
                acc2[i][0] = fma2(xx[i], wv.x, acc2[i][0]);
                acc2[i][1] = fma2(xx[i], wv.y, acc2[i][1]);
            }
        }
        float bb[4];
#pragma unroll
        for (int j = 0; j < 4; j++) bb[j] = b1[cb + j];
        float sl[4] = {0,0,0,0}, ssl[4] = {0,0,0,0};
#pragma unroll
        for (int i = 0; i < 4; i++) {
            float2 a0 = unpack2(acc2[i][0]);
            float2 a1 = unpack2(acc2[i][1]);
            float4 hv;
            hv.x = a0.x + bb[0]; hv.y = a0.y + bb[1];
            hv.z = a1.x + bb[2]; hv.w = a1.y + bb[3];
            *(float4*)&g_h1[(rowg + rb + i) * 64 + cb] = hv;
            sl[0] += hv.x; ssl[0] += hv.x * hv.x;
            sl[1] += hv.y; ssl[1] += hv.y * hv.y;
            sl[2] += hv.z; ssl[2] += hv.z * hv.z;
            sl[3] += hv.w; ssl[3] += hv.w * hv.w;
        }
#pragma unroll
        for (int off = 16; off >= 4; off >>= 1) {
#pragma unroll
            for (int j = 0; j < 4; j++) {
                sl[j]  += __shfl_down_sync(0xFFFFFFFFu, sl[j],  off);
                ssl[j] += __shfl_down_sync(0xFFFFFFFFu, ssl[j], off);
            }
        }
        if (lr == 0) {
#pragma unroll
            for (int j = 0; j < 4; j++) {
                stu[wr * 64 + cb + j]       = sl[j];
                stu[128 + wr * 64 + cb + j] = ssl[j];
            }
        }
        __syncthreads();
        if (tid < 128) {
            int uu = tid >> 6, ch = tid & 63;
            float* sb = st + uu * 256;
            g_sumA[(size_t)ch * CBLKS + (wp * 2 + uu)] = sb[ch] + sb[64 + ch];
            g_ssqA[(size_t)ch * CBLKS + (wp * 2 + uu)] = sb[128 + ch] + sb[192 + ch];
        }
        __syncthreads();
    }

    {   // ---- geo (CIN=6) ----
        float* Xg = XsG + u * 64 * 7;
        unsigned long long acc2[4][2];
#pragma unroll
        for (int i = 0; i < 4; i++) { acc2[i][0] = 0ull; acc2[i][1] = 0ull; }
#pragma unroll
        for (int k = 0; k < 6; k++) {
            unsigned long long xx[4];
#pragma unroll
            for (int i = 0; i < 4; i++) xx[i] = pack2(Xg[(rb + i) * 7 + k]);
            ulonglong2 wv = *(const ulonglong2*)&WsG[k * 64 + cb];
#pragma unroll
            for (int i = 0; i < 4; i++) {
                acc2[i][0] = fma2(xx[i], wv.x, acc2[i][0]);
                acc2[i][1] = fma2(xx[i], wv.y, acc2[i][1]);
            }
        }
        float bb[4];
#pragma unroll
        for (int j = 0; j < 4; j++) bb[j] = bg[cb + j];
        float sl[4] = {0,0,0,0}, ssl[4] = {0,0,0,0};
#pragma unroll
        for (int i = 0; i < 4; i++) {
            float2 a0 = unpack2(acc2[i][0]);
            float2 a1 = unpack2(acc2[i][1]);
            float4 hv;
            hv.x = a0.x + bb[0]; hv.y = a0.y + bb[1];
            hv.z = a1.x + bb[2]; hv.w = a1.y + bb[3];
            *(float4*)&g_h1b[(rowg + rb + i) * 64 + cb] = hv;
            sl[0] += hv.x; ssl[0] += hv.x * hv.x;
            sl[1] += hv.y; ssl[1] += hv.y * hv.y;
            sl[2] += hv.z; ssl[2] += hv.z * hv.z;
            sl[3] += hv.w; ssl[3] += hv.w * hv.w;
        }
#pragma unroll
        for (int off = 16; off >= 4; off >>= 1) {
#pragma unroll
            for (int j = 0; j < 4; j++) {
                sl[j]  += __shfl_down_sync(0xFFFFFFFFu, sl[j],  off);
                ssl[j] += __shfl_down_sync(0xFFFFFFFFu, ssl[j], off);
            }
        }
        if (lr == 0) {
#pragma unroll
            for (int j = 0; j < 4; j++) {
                stu[wr * 64 + cb + j]       = sl[j];
                stu[128 + wr * 64 + cb + j] = ssl[j];
            }
        }
        __syncthreads();
        if (tid < 128) {
            int uu = tid >> 6, ch = tid & 63;
            float* sb = st + uu * 256;
            g_sumB[(size_t)ch * CBLKS + (wp * 2 + uu)] = sb[ch] + sb[64 + ch];
            g_ssqB[(size_t)ch * CBLKS + (wp * 2 + uu)] = sb[128 + ch] + sb[192 + ch];
        }
    }
}

// =====================================================================
// conv2: R14 version, parameterized h1 source; partials -> g_sumC/g_ssqC.
// =====================================================================
#define C2_XS (64 * 65)
#define C2_SMEM ((C2_XS + 64 * 128) * (int)sizeof(float))

__global__ __launch_bounds__(256)
void conv2_kernel(const float* __restrict__ h1, const float* __restrict__ W,
                  const float* __restrict__ bias) {
    extern __shared__ float dsm[];
    float* Xs = dsm;
    float* Ws = dsm + C2_XS;
    const int row0 = blockIdx.x * 64;
    const int tid = threadIdx.x;

    for (int i = tid; i < 64 * 128 / 4; i += 256)
        ((float4*)Ws)[i] = ((const float4*)W)[i];
    for (int i = tid; i < 64 * 16; i += 256) {
        int r = i >> 4, c4 = (i & 15) * 4;
        float4 h = *(const float4*)&h1[(size_t)(row0 + r) * 64 + c4];
        float4 A = *(const float4*)&g_a[c4];
        float4 C = *(const float4*)&g_c[c4];
        float* xr = &Xs[r * 65 + c4];
        xr[0] = fmaxf(0.0f, fmaf(A.x, h.x, C.x));
        xr[1] = fmaxf(0.0f, fmaf(A.y, h.y, C.y));
        xr[2] = fmaxf(0.0f, fmaf(A.z, h.z, C.z));
        xr[3] = fmaxf(0.0f, fmaf(A.w, h.w, C.w));
    }
    __syncthreads();

    const int warp = tid >> 5, lane = tid & 31;
    const int wr = warp & 1;
    const int wc = warp >> 1;
    const int lr = lane >> 2;
    const int lc = lane & 3;
    const int rb = wr * 32 + lr * 4;
    const int cb = wc * 32 + lc * 8;

    unsigned long long acc2[4][4];
#pragma unroll
    for (int i = 0; i < 4; i++)
#pragma unroll
        for (int j = 0; j < 4; j++) acc2[i][j] = 0ull;

#pragma unroll 8
    for (int k = 0; k < 64; k++) {
        unsigned long long xx[4];
#pragma unroll
        for (int i = 0; i < 4; i++) xx[i] = pack2(Xs[(rb + i) * 65 + k]);
        ulonglong2 wa = *(const ulonglong2*)&Ws[k * 128 + cb];
        ulonglong2 wb = *(const ulonglong2*)&Ws[k * 128 + cb + 4];
#pragma unroll
        for (int i = 0; i < 4; i++) {
            acc2[i][0] = fma2(xx[i], wa.x, acc2[i][0]);
            acc2[i][1] = fma2(xx[i], wa.y, acc2[i][1]);
            acc2[i][2] = fma2(xx[i], wb.x, acc2[i][2]);
            acc2[i][3] = fma2(xx[i], wb.y, acc2[i][3]);
        }
    }

    float acc[4][8];
#pragma unroll
    for (int i = 0; i < 4; i++)
#pragma unroll
        for (int j = 0; j < 4; j++) {
            float2 v = unpack2(acc2[i][j]);
            acc[i][j * 2]     = v.x;
            acc[i][j * 2 + 1] = v.y;
        }

    float bb[8];
#pragma unroll
    for (int j = 0; j < 8; j++) bb[j] = bias[cb + j];
    float sl[8], ssl[8], mxl[8], mnl[8];
#pragma unroll
    for (int j = 0; j < 8; j++) {
        sl[j] = 0.0f; ssl[j] = 0.0f;
        mxl[j] = -3.402823466e38f; mnl[j] = 3.402823466e38f;
    }
#pragma unroll
    for (int i = 0; i < 4; i++)
#pragma unroll
        for (int j = 0; j < 8; j++) {
            float h = acc[i][j] + bb[j];
            sl[j] += h; ssl[j] += h * h;
            mxl[j] = fmaxf(mxl[j], h); mnl[j] = fminf(mnl[j], h);
        }

#pragma unroll
    for (int off = 16; off >= 4; off >>= 1) {
#pragma unroll
        for (int j = 0; j < 8; j++) {
            sl[j]  += __shfl_down_sync(0xFFFFFFFFu, sl[j],  off);
            ssl[j] += __shfl_down_sync(0xFFFFFFFFu, ssl[j], off);
            mxl[j] = fmaxf(mxl[j], __shfl_down_sync(0xFFFFFFFFu, mxl[j], off));
            mnl[j] = fminf(mnl[j], __shfl_down_sync(0xFFFFFFFFu, mnl[j], off));
        }
    }

    float* st = Xs;
    __syncthreads();
    if (lr == 0) {
        int blk = blockIdx.x;
#pragma unroll
        for (int j = 0; j < 8; j++) {
            int c = cb + j;
            g_mx[(size_t)(blk * 2 + wr) * 128 + c] = mxl[j];
            g_mn[(size_t)(blk * 2 + wr) * 128 + c] = mnl[j];
            st[wr * 128 + c]       = sl[j];
            st[256 + wr * 128 + c] = ssl[j];
        }
    }
    __syncthreads();
    if (tid < 128) {
        float S  = st[tid] + st[128 + tid];
        float SS = st[256 + tid] + st[384 + tid];
        g_sumC[(size_t)tid * CBLKS + blockIdx.x] = S;
        g_ssqC[(size_t)tid * CBLKS + blockIdx.x] = SS;
    }
}

// =====================================================================
// BN finalize: parameterized partial arrays; float4 reads, fp64 tree.
// =====================================================================
__global__ __launch_bounds__(256)
void finalize_stats(const float* __restrict__ sum, const float* __restrict__ ssq,
                    const float* __restrict__ gamma, const float* __restrict__ beta) {
    const int ch = blockIdx.x;
    const int t = threadIdx.x;
    __shared__ double rs[256], rss[256];
    double S = 0.0, SS = 0.0;
#pragma unroll
    for (int i = 0; i < 4; i++) {
        float4 a = *(const float4*)&sum[(size_t)ch * CBLKS + i * 1024 + t * 4];
        float4 b = *(const float4*)&ssq[(size_t)ch * CBLKS + i * 1024 + t * 4];
        S  += (double)a.x + (double)a.y + (double)a.z + (double)a.w;
        SS += (double)b.x + (double)b.y + (double)b.z + (double)b.w;
    }
    rs[t] = S; rss[t] = SS;
    __syncthreads();
    for (int off = 128; off; off >>= 1) {
        if (t < off) { rs[t] += rs[t + off]; rss[t] += rss[t + off]; }
        __syncthreads();
    }
    if (t == 0) {
        double inv_n = 1.0 / (double)NROWS;
        double mu  = rs[0] * inv_n;
        double var = rss[0] * inv_n - mu * mu;
        double a = (double)gamma[ch] / sqrt(var + 1e-5);
        g_a[ch] = (float)a;
        g_c[ch] = (float)((double)beta[ch] - mu * a);
    }
}

// =====================================================================
// Output: relu(a * extreme(h2) + c).
// =====================================================================
__global__ void final_out(float* __restrict__ out) {
    const int cc = blockIdx.x;
    const int ch = threadIdx.x;
    float a = g_a[ch];
    float ext = (a >= 0.0f) ? g_mx[(size_t)cc * 128 + ch] : g_mn[(size_t)cc * 128 + ch];
    out[(size_t)cc * 128 + ch] = fmaxf(0.0f, fmaf(a, ext, g_c[ch]));
}

// =====================================================================
extern "C" void kernel_launch(void* const* d_in, const int* in_sizes, int n_in,
                              void* d_out, int out_size) {
    const float* pos     = (const float*)d_in[0];
    const float* feat    = (const float*)d_in[1];
    const float* w_sem1  = (const float*)d_in[2];
    const float* b_sem1  = (const float*)d_in[3];
    const float* g_sem1  = (const float*)d_in[4];
    const float* be_sem1 = (const float*)d_in[5];
    const float* w_sem2  = (const float*)d_in[6];
    const float* b_sem2  = (const float*)d_in[7];
    const float* g_sem2  = (const float*)d_in[8];
    const float* be_sem2 = (const float*)d_in[9];
    const float* w_geo1  = (const float*)d_in[10];
    const float* b_geo1  = (const float*)d_in[11];
    const float* g_geo1  = (const float*)d_in[12];
    const float* be_geo1 = (const float*)d_in[13];
    const float* w_geo2  = (const float*)d_in[14];
    const float* b_geo2  = (const float*)d_in[15];
    const float* g_geo2  = (const float*)d_in[16];
    const float* be_geo2 = (const float*)d_in[17];
    float* out = (float*)d_out;

    cudaFuncSetAttribute(fused_kernel, cudaFuncAttributeMaxDynamicSharedMemorySize,
                         FUSED_SMEM);
    cudaFuncSetAttribute(conv2_kernel, cudaFuncAttributeMaxDynamicSharedMemorySize,
                         C2_SMEM);

    float *h1p = nullptr, *h1bp = nullptr;
    float *sumA = nullptr, *ssqA = nullptr, *sumB = nullptr, *ssqB = nullptr;
    float *sumC = nullptr, *ssqC = nullptr;
    cudaGetSymbolAddress((void**)&h1p,  g_h1);
    cudaGetSymbolAddress((void**)&h1bp, g_h1b);
    cudaGetSymbolAddress((void**)&sumA, g_sumA);
    cudaGetSymbolAddress((void**)&ssqA, g_ssqA);
    cudaGetSymbolAddress((void**)&sumB, g_sumB);
    cudaGetSymbolAddress((void**)&ssqB, g_ssqB);
    cudaGetSymbolAddress((void**)&sumC, g_sumC);
    cudaGetSymbolAddress((void**)&ssqC, g_ssqC);

    fused_kernel<<<GRID_, FPS_T, FUSED_SMEM>>>(pos, feat, w_sem1, b_sem1,
                                               w_geo1, b_geo1);

    // ---- SEM branch ----
    finalize_stats<<<64, 256>>>(sumA, ssqA, g_sem1, be_sem1);
    conv2_kernel<<<CBLKS, 256, C2_SMEM>>>(h1p, w_sem2, b_sem2);
    finalize_stats<<<128, 256>>>(sumC, ssqC, g_sem2, be_sem2);
    final_out<<<NCC, 128>>>(out);

    // ---- GEO branch ----
    finalize_stats<<<64, 256>>>(sumB, ssqB, g_geo1, be_geo1);
    conv2_kernel<<<CBLKS, 256, C2_SMEM>>>(h1bp, w_geo2, b_geo2);
    finalize_stats<<<128, 256>>>(sumC, ssqC, g_geo2, be_geo2);
    final_out<<<NCC, 128>>>(out + (size_t)NCC * 128);
}